// round 13
// baseline (speedup 1.0000x reference)
#include <cuda_runtime.h>
#include <math.h>

#define B 64
#define T 4096
#define D 512
#define SPLITS 64
#define CHUNK (T / SPLITS)          // 64 rows of T per CTA
#define THREADS 256                 // 8 warps per CTA
#define ROWS_PER_WARP (CHUNK / 8)   // 8

// Scratch (no allocation allowed anywhere)
__device__ float g_k[B * D];
__device__ float g_pm[B * SPLITS];
__device__ float g_ps[B * SPLITS];
__device__ float g_pacc[B * SPLITS * D];        // 8 MB

// ---------------------------------------------------------------------------
// Kernel 1: k = query @ W^T + bias.  Warp computes a 4b x 4d tile.
// (unchanged from R12: 7.8us, not the bottleneck)
// ---------------------------------------------------------------------------
__global__ __launch_bounds__(256)
void key_kernel(const float* __restrict__ query,
                const float* __restrict__ W,
                const float* __restrict__ bias) {
    const int wid  = threadIdx.x >> 5;
    const int lane = threadIdx.x & 31;
    const int warp = blockIdx.x * 8 + wid;      // 0..2047
    const int d0   = (warp & 127) * 4;          // 128 d-tiles
    const int b0   = (warp >> 7) * 4;           // 16  b-tiles

    const float4* Wp = (const float4*)W;        // row = 128 float4
    const float4* Qp = (const float4*)query;

    float4 w[4][4];
    #pragma unroll
    for (int i = 0; i < 4; i++)
        #pragma unroll
        for (int j = 0; j < 4; j++)
            w[i][j] = Wp[(size_t)(d0 + i) * 128 + lane + 32 * j];

    #pragma unroll
    for (int bi = 0; bi < 4; bi++) {
        float4 q4[4];
        #pragma unroll
        for (int j = 0; j < 4; j++)
            q4[j] = Qp[(size_t)(b0 + bi) * 128 + lane + 32 * j];

        float p[4];
        #pragma unroll
        for (int i = 0; i < 4; i++) {
            float s0 = 0.f, s1 = 0.f, s2 = 0.f, s3 = 0.f;
            #pragma unroll
            for (int j = 0; j < 4; j++) {
                s0 = fmaf(w[i][j].x, q4[j].x, s0);
                s1 = fmaf(w[i][j].y, q4[j].y, s1);
                s2 = fmaf(w[i][j].z, q4[j].z, s2);
                s3 = fmaf(w[i][j].w, q4[j].w, s3);
            }
            p[i] = (s0 + s1) + (s2 + s3);
        }
        #pragma unroll
        for (int off = 16; off; off >>= 1)
            #pragma unroll
            for (int i = 0; i < 4; i++)
                p[i] += __shfl_xor_sync(0xffffffffu, p[i], off);
        if (lane == 0) {
            #pragma unroll
            for (int i = 0; i < 4; i++)
                g_k[(size_t)(b0 + bi) * D + d0 + i] = p[i] + bias[d0 + i];
        }
    }
}

// ---------------------------------------------------------------------------
// Kernel 2: fused scores + masked online softmax + weighted accumulation.
// grid = (SPLITS, B) = 4096 CTAs. Warp-owns-row register streaming with
// 2-row-deep prefetch (8 outstanding LDG.128/lane -> ~500cyc lead over use).
// min-blocks=2 so ptxas has 128 regs (no spills with c+n1+n2+a = 64 regs).
// ---------------------------------------------------------------------------
__global__ __launch_bounds__(THREADS, 2)
void attn_partial_kernel(const float* __restrict__ attend_to,
                         const int* __restrict__ mask) {   // bool -> int32
    __shared__ float  k_sh[D];                 // 2 KB
    __shared__ float4 sm_acc[8][D / 4];        // 16 KB (end-phase)
    __shared__ float  sm_m[8], sm_s[8];

    const int b    = blockIdx.y;
    const int sp   = blockIdx.x;
    const int tid  = threadIdx.x;
    const int wid  = tid >> 5;
    const int lane = tid & 31;
    const int trow0 = sp * CHUNK + wid * ROWS_PER_WARP;

    for (int i = tid; i < D; i += THREADS) k_sh[i] = g_k[(size_t)b * D + i];

    // Warp's ROWS_PER_WARP(=8) mask bits gathered into one ballot word.
    int mv = 0;
    if (lane < ROWS_PER_WARP)
        mv = __ldg(&mask[(size_t)(trow0 + lane) * B + b]);
    const unsigned mbits = __ballot_sync(0xffffffffu, mv != 0);

    const float4* rp = (const float4*)(attend_to + ((size_t)b * T + trow0) * D);

    // Prologue: rows 0 and 1 in flight
    float4 c0 = rp[lane],       c1 = rp[lane + 32],
           c2 = rp[lane + 64],  c3 = rp[lane + 96];
    const float4* r1 = rp + (D / 4);
    float4 n10 = r1[lane],      n11 = r1[lane + 32],
           n12 = r1[lane + 64], n13 = r1[lane + 96];

    __syncthreads();                           // k_sh ready
    const float4* ks4 = (const float4*)k_sh;

    float m = -INFINITY, s = 0.f;
    float4 a0 = {0,0,0,0}, a1 = {0,0,0,0}, a2 = {0,0,0,0}, a3 = {0,0,0,0};

    #pragma unroll
    for (int i = 0; i < ROWS_PER_WARP; i++) {
        // Issue row i+2 loads first (2-deep pipeline)
        float4 n20, n21, n22, n23;
        if (i + 2 < ROWS_PER_WARP) {
            const float4* nr = rp + (size_t)(i + 2) * (D / 4);
            n20 = nr[lane];      n21 = nr[lane + 32];
            n22 = nr[lane + 64]; n23 = nr[lane + 96];
        }

        // Row i dot with k (k slice from smem, transient regs)
        float4 kv = ks4[lane];
        float p0 = c0.x * kv.x + c0.y * kv.y + c0.z * kv.z + c0.w * kv.w;
        kv = ks4[lane + 32];
        float p1 = c1.x * kv.x + c1.y * kv.y + c1.z * kv.z + c1.w * kv.w;
        kv = ks4[lane + 64];
        float p2 = c2.x * kv.x + c2.y * kv.y + c2.z * kv.z + c2.w * kv.w;
        kv = ks4[lane + 96];
        float p3 = c3.x * kv.x + c3.y * kv.y + c3.z * kv.z + c3.w * kv.w;
        float sc = (p0 + p1) + (p2 + p3);
        #pragma unroll
        for (int off = 16; off; off >>= 1)
            sc += __shfl_xor_sync(0xffffffffu, sc, off);
        if ((mbits >> i) & 1u) sc = -INFINITY;

        // Online softmax update (branches warp-uniform)
        if (sc > m) {
            float corr = __expf(m - sc);       // m=-inf -> corr=0 on first row
            s = s * corr + 1.0f;
            a0.x = fmaf(a0.x, corr, c0.x); a0.y = fmaf(a0.y, corr, c0.y);
            a0.z = fmaf(a0.z, corr, c0.z); a0.w = fmaf(a0.w, corr, c0.w);
            a1.x = fmaf(a1.x, corr, c1.x); a1.y = fmaf(a1.y, corr, c1.y);
            a1.z = fmaf(a1.z, corr, c1.z); a1.w = fmaf(a1.w, corr, c1.w);
            a2.x = fmaf(a2.x, corr, c2.x); a2.y = fmaf(a2.y, corr, c2.y);
            a2.z = fmaf(a2.z, corr, c2.z); a2.w = fmaf(a2.w, corr, c2.w);
            a3.x = fmaf(a3.x, corr, c3.x); a3.y = fmaf(a3.y, corr, c3.y);
            a3.z = fmaf(a3.z, corr, c3.z); a3.w = fmaf(a3.w, corr, c3.w);
            m = sc;
        } else if (sc != -INFINITY) {
            float p = __expf(sc - m);
            s += p;
            a0.x = fmaf(p, c0.x, a0.x); a0.y = fmaf(p, c0.y, a0.y);
            a0.z = fmaf(p, c0.z, a0.z); a0.w = fmaf(p, c0.w, a0.w);
            a1.x = fmaf(p, c1.x, a1.x); a1.y = fmaf(p, c1.y, a1.y);
            a1.z = fmaf(p, c1.z, a1.z); a1.w = fmaf(p, c1.w, a1.w);
            a2.x = fmaf(p, c2.x, a2.x); a2.y = fmaf(p, c2.y, a2.y);
            a2.z = fmaf(p, c2.z, a2.z); a2.w = fmaf(p, c2.w, a2.w);
            a3.x = fmaf(p, c3.x, a3.x); a3.y = fmaf(p, c3.y, a3.y);
            a3.z = fmaf(p, c3.z, a3.z); a3.w = fmaf(p, c3.w, a3.w);
        }
        // Rotate pipeline registers
        c0 = n10; c1 = n11; c2 = n12; c3 = n13;
        n10 = n20; n11 = n21; n12 = n22; n13 = n23;
    }

    // ---- End-phase: combine 8 warps -> one CTA partial ----
    sm_acc[wid][lane]      = a0;
    sm_acc[wid][lane + 32] = a1;
    sm_acc[wid][lane + 64] = a2;
    sm_acc[wid][lane + 96] = a3;
    if (lane == 0) { sm_m[wid] = m; sm_s[wid] = s; }
    __syncthreads();

    float M = -INFINITY;
    #pragma unroll
    for (int w = 0; w < 8; w++) M = fmaxf(M, sm_m[w]);
    float wts[8];
    float stot = 0.f;
    #pragma unroll
    for (int w = 0; w < 8; w++) {
        float mw = sm_m[w];
        float wt = (mw == -INFINITY) ? 0.f : __expf(mw - M);
        wts[w] = wt;
        stot += wt * sm_s[w];
    }

    const float* sa = (const float*)sm_acc;   // [8][512]
    float v0 = 0.f, v1 = 0.f;
    #pragma unroll
    for (int w = 0; w < 8; w++) {
        v0 += wts[w] * sa[w * D + tid];
        v1 += wts[w] * sa[w * D + tid + THREADS];
    }

    const int pi = b * SPLITS + sp;
    g_pacc[(size_t)pi * D + tid]           = v0;
    g_pacc[(size_t)pi * D + tid + THREADS] = v1;
    if (tid == 0) { g_pm[pi] = M; g_ps[pi] = stot; }
}

// ---------------------------------------------------------------------------
// Kernel 3: combine SPLITS partials per batch row. grid = (B, 2).
// ---------------------------------------------------------------------------
__global__ __launch_bounds__(256)
void combine_kernel(float* __restrict__ out) {
    const int b = blockIdx.x;
    const int c = blockIdx.y * 256 + threadIdx.x;

    float M = -INFINITY;
    #pragma unroll 8
    for (int i = 0; i < SPLITS; i++) M = fmaxf(M, g_pm[b * SPLITS + i]);

    float stot = 0.f, sum = 0.f;
    #pragma unroll 8
    for (int i = 0; i < SPLITS; i++) {
        float mi = g_pm[b * SPLITS + i];
        float w = (mi == -INFINITY) ? 0.f : __expf(mi - M);
        stot += g_ps[b * SPLITS + i] * w;
        sum  += g_pacc[(size_t)(b * SPLITS + i) * D + c] * w;
    }
    out[(size_t)b * D + c] = sum / stot;
}

// ---------------------------------------------------------------------------
// Inputs (metadata order): query [B,D] f32, attend_to [B,T,D] f32,
// mask [T,B] bool->int32, W [D,D] f32, b [D] f32. Output: [B,1,D] f32.
// ---------------------------------------------------------------------------
extern "C" void kernel_launch(void* const* d_in, const int* in_sizes, int n_in,
                              void* d_out, int out_size) {
    const float* query  = (const float*)d_in[0];
    const float* attend = (const float*)d_in[1];
    const int*   mask   = (const int*)d_in[2];
    const float* W      = (const float*)d_in[3];
    const float* bias   = (const float*)d_in[4];
    float* out = (float*)d_out;

    key_kernel<<<256, 256>>>(query, W, bias);
    attn_partial_kernel<<<dim3(SPLITS, B), THREADS>>>(attend, mask);
    combine_kernel<<<dim3(B, 2), 256>>>(out);
}

// round 14
// speedup vs baseline: 1.1120x; 1.1120x over previous
#include <cuda_runtime.h>
#include <math.h>

#define B 64
#define T 4096
#define D 512
#define SPLITS 32
#define CHUNK (T / SPLITS)          // 128 rows of T per CTA
#define THREADS 256                 // 8 warps per CTA
#define ROWS_PER_WARP (CHUNK / 8)   // 16

// Scratch (no allocation allowed anywhere)
__device__ float g_k[B * D];
__device__ float g_pm[B * SPLITS];
__device__ float g_ps[B * SPLITS];
__device__ float g_pacc[B * SPLITS * D];        // 4 MB

// ---------------------------------------------------------------------------
// Kernel 1: k = query @ W^T + bias.  Warp computes a 4b x 4d tile.
// 128-thread CTAs (4 warps), grid 512: same warp tiling / same L2 traffic as
// R12 but finer CTA granularity -> 3.46 CTAs/SM, less wave quantization.
// ---------------------------------------------------------------------------
__global__ __launch_bounds__(128)
void key_kernel(const float* __restrict__ query,
                const float* __restrict__ W,
                const float* __restrict__ bias) {
    const int wid  = threadIdx.x >> 5;
    const int lane = threadIdx.x & 31;
    const int warp = blockIdx.x * 4 + wid;      // 0..2047
    const int d0   = (warp & 127) * 4;          // 128 d-tiles
    const int b0   = (warp >> 7) * 4;           // 16  b-tiles

    const float4* Wp = (const float4*)W;        // row = 128 float4
    const float4* Qp = (const float4*)query;

    float4 w[4][4];
    #pragma unroll
    for (int i = 0; i < 4; i++)
        #pragma unroll
        for (int j = 0; j < 4; j++)
            w[i][j] = Wp[(size_t)(d0 + i) * 128 + lane + 32 * j];

    #pragma unroll
    for (int bi = 0; bi < 4; bi++) {
        float4 q4[4];
        #pragma unroll
        for (int j = 0; j < 4; j++)
            q4[j] = Qp[(size_t)(b0 + bi) * 128 + lane + 32 * j];

        float p[4];
        #pragma unroll
        for (int i = 0; i < 4; i++) {
            float s0 = 0.f, s1 = 0.f, s2 = 0.f, s3 = 0.f;
            #pragma unroll
            for (int j = 0; j < 4; j++) {
                s0 = fmaf(w[i][j].x, q4[j].x, s0);
                s1 = fmaf(w[i][j].y, q4[j].y, s1);
                s2 = fmaf(w[i][j].z, q4[j].z, s2);
                s3 = fmaf(w[i][j].w, q4[j].w, s3);
            }
            p[i] = (s0 + s1) + (s2 + s3);
        }
        #pragma unroll
        for (int off = 16; off; off >>= 1)
            #pragma unroll
            for (int i = 0; i < 4; i++)
                p[i] += __shfl_xor_sync(0xffffffffu, p[i], off);
        if (lane == 0) {
            #pragma unroll
            for (int i = 0; i < 4; i++)
                g_k[(size_t)(b0 + bi) * D + d0 + i] = p[i] + bias[d0 + i];
        }
    }
}

// ---------------------------------------------------------------------------
// Kernel 2: fused scores + masked online softmax + weighted accumulation.
// EXACT R12 version (measured ~93us): grid (SPLITS, B), warp-owns-row
// register streaming, 1-row prefetch, k from smem, 3 CTAs/SM.
// ---------------------------------------------------------------------------
__global__ __launch_bounds__(THREADS, 3)
void attn_partial_kernel(const float* __restrict__ attend_to,
                         const int* __restrict__ mask) {   // bool -> int32
    __shared__ float  k_sh[D];                 // 2 KB
    __shared__ float4 sm_acc[8][D / 4];        // 16 KB (end-phase)
    __shared__ float  sm_m[8], sm_s[8];

    const int b    = blockIdx.y;
    const int sp   = blockIdx.x;
    const int tid  = threadIdx.x;
    const int wid  = tid >> 5;
    const int lane = tid & 31;
    const int trow0 = sp * CHUNK + wid * ROWS_PER_WARP;

    for (int i = tid; i < D; i += THREADS) k_sh[i] = g_k[(size_t)b * D + i];

    // Warp's ROWS_PER_WARP(=16) mask bits gathered into one ballot word.
    int mv = 0;
    if (lane < ROWS_PER_WARP)
        mv = __ldg(&mask[(size_t)(trow0 + lane) * B + b]);
    const unsigned mbits = __ballot_sync(0xffffffffu, mv != 0);

    const float4* rp = (const float4*)(attend_to + ((size_t)b * T + trow0) * D);
    float4 c0 = rp[lane], c1 = rp[lane + 32],
           c2 = rp[lane + 64], c3 = rp[lane + 96];

    __syncthreads();                           // k_sh ready
    const float4* ks4 = (const float4*)k_sh;

    float m = -INFINITY, s = 0.f;
    float4 a0 = {0,0,0,0}, a1 = {0,0,0,0}, a2 = {0,0,0,0}, a3 = {0,0,0,0};

    #pragma unroll 2
    for (int i = 0; i < ROWS_PER_WARP; i++) {
        // Prefetch next row into registers
        float4 n0, n1, n2, n3;
        if (i + 1 < ROWS_PER_WARP) {
            const float4* nr = rp + (size_t)(i + 1) * (D / 4);
            n0 = nr[lane]; n1 = nr[lane + 32];
            n2 = nr[lane + 64]; n3 = nr[lane + 96];
        }

        // Row dot with k (k slice from smem, transient regs)
        float4 kv = ks4[lane];
        float p0 = c0.x * kv.x + c0.y * kv.y + c0.z * kv.z + c0.w * kv.w;
        kv = ks4[lane + 32];
        float p1 = c1.x * kv.x + c1.y * kv.y + c1.z * kv.z + c1.w * kv.w;
        kv = ks4[lane + 64];
        float p2 = c2.x * kv.x + c2.y * kv.y + c2.z * kv.z + c2.w * kv.w;
        kv = ks4[lane + 96];
        float p3 = c3.x * kv.x + c3.y * kv.y + c3.z * kv.z + c3.w * kv.w;
        float sc = (p0 + p1) + (p2 + p3);
        #pragma unroll
        for (int off = 16; off; off >>= 1)
            sc += __shfl_xor_sync(0xffffffffu, sc, off);
        if ((mbits >> i) & 1u) sc = -INFINITY;

        // Online softmax update (branches warp-uniform)
        if (sc > m) {
            float corr = __expf(m - sc);       // m=-inf -> corr=0 on first row
            s = s * corr + 1.0f;
            a0.x = fmaf(a0.x, corr, c0.x); a0.y = fmaf(a0.y, corr, c0.y);
            a0.z = fmaf(a0.z, corr, c0.z); a0.w = fmaf(a0.w, corr, c0.w);
            a1.x = fmaf(a1.x, corr, c1.x); a1.y = fmaf(a1.y, corr, c1.y);
            a1.z = fmaf(a1.z, corr, c1.z); a1.w = fmaf(a1.w, corr, c1.w);
            a2.x = fmaf(a2.x, corr, c2.x); a2.y = fmaf(a2.y, corr, c2.y);
            a2.z = fmaf(a2.z, corr, c2.z); a2.w = fmaf(a2.w, corr, c2.w);
            a3.x = fmaf(a3.x, corr, c3.x); a3.y = fmaf(a3.y, corr, c3.y);
            a3.z = fmaf(a3.z, corr, c3.z); a3.w = fmaf(a3.w, corr, c3.w);
            m = sc;
        } else if (sc != -INFINITY) {
            float p = __expf(sc - m);
            s += p;
            a0.x = fmaf(p, c0.x, a0.x); a0.y = fmaf(p, c0.y, a0.y);
            a0.z = fmaf(p, c0.z, a0.z); a0.w = fmaf(p, c0.w, a0.w);
            a1.x = fmaf(p, c1.x, a1.x); a1.y = fmaf(p, c1.y, a1.y);
            a1.z = fmaf(p, c1.z, a1.z); a1.w = fmaf(p, c1.w, a1.w);
            a2.x = fmaf(p, c2.x, a2.x); a2.y = fmaf(p, c2.y, a2.y);
            a2.z = fmaf(p, c2.z, a2.z); a2.w = fmaf(p, c2.w, a2.w);
            a3.x = fmaf(p, c3.x, a3.x); a3.y = fmaf(p, c3.y, a3.y);
            a3.z = fmaf(p, c3.z, a3.z); a3.w = fmaf(p, c3.w, a3.w);
        }
        c0 = n0; c1 = n1; c2 = n2; c3 = n3;
    }

    // ---- End-phase: combine 8 warps -> one CTA partial ----
    sm_acc[wid][lane]      = a0;
    sm_acc[wid][lane + 32] = a1;
    sm_acc[wid][lane + 64] = a2;
    sm_acc[wid][lane + 96] = a3;
    if (lane == 0) { sm_m[wid] = m; sm_s[wid] = s; }
    __syncthreads();

    float M = -INFINITY;
    #pragma unroll
    for (int w = 0; w < 8; w++) M = fmaxf(M, sm_m[w]);
    float wts[8];
    float stot = 0.f;
    #pragma unroll
    for (int w = 0; w < 8; w++) {
        float mw = sm_m[w];
        float wt = (mw == -INFINITY) ? 0.f : __expf(mw - M);
        wts[w] = wt;
        stot += wt * sm_s[w];
    }

    const float* sa = (const float*)sm_acc;   // [8][512]
    float v0 = 0.f, v1 = 0.f;
    #pragma unroll
    for (int w = 0; w < 8; w++) {
        v0 += wts[w] * sa[w * D + tid];
        v1 += wts[w] * sa[w * D + tid + THREADS];
    }

    const int pi = b * SPLITS + sp;
    g_pacc[(size_t)pi * D + tid]           = v0;
    g_pacc[(size_t)pi * D + tid + THREADS] = v1;
    if (tid == 0) { g_pm[pi] = M; g_ps[pi] = stot; }
}

// ---------------------------------------------------------------------------
// Kernel 3: combine SPLITS partials per batch row. grid = (B, 2).
// ---------------------------------------------------------------------------
__global__ __launch_bounds__(256)
void combine_kernel(float* __restrict__ out) {
    const int b = blockIdx.x;
    const int c = blockIdx.y * 256 + threadIdx.x;

    float M = -INFINITY;
    #pragma unroll
    for (int i = 0; i < SPLITS; i++) M = fmaxf(M, g_pm[b * SPLITS + i]);

    float stot = 0.f, sum = 0.f;
    #pragma unroll
    for (int i = 0; i < SPLITS; i++) {
        float mi = g_pm[b * SPLITS + i];
        float w = (mi == -INFINITY) ? 0.f : __expf(mi - M);
        stot += g_ps[b * SPLITS + i] * w;
        sum  += g_pacc[(size_t)(b * SPLITS + i) * D + c] * w;
    }
    out[(size_t)b * D + c] = sum / stot;
}

// ---------------------------------------------------------------------------
// Inputs (metadata order): query [B,D] f32, attend_to [B,T,D] f32,
// mask [T,B] bool->int32, W [D,D] f32, b [D] f32. Output: [B,1,D] f32.
// ---------------------------------------------------------------------------
extern "C" void kernel_launch(void* const* d_in, const int* in_sizes, int n_in,
                              void* d_out, int out_size) {
    const float* query  = (const float*)d_in[0];
    const float* attend = (const float*)d_in[1];
    const int*   mask   = (const int*)d_in[2];
    const float* W      = (const float*)d_in[3];
    const float* bias   = (const float*)d_in[4];
    float* out = (float*)d_out;

    key_kernel<<<512, 128>>>(query, W, bias);
    attn_partial_kernel<<<dim3(SPLITS, B), THREADS>>>(attend, mask);
    combine_kernel<<<dim3(B, 2), 256>>>(out);
}